// round 16
// baseline (speedup 1.0000x reference)
#include <cuda_runtime.h>
#include <cuda_fp16.h>

#define TT 4096
#define DD 1024
#define FF 4096
#define EE 8
#define NROWS (TT * 2)
#define NW   (EE * FF * DD)

typedef unsigned int u32;

// ================= device scratch (static) =================
__device__ __half g_xh[TT * DD];
__device__ __half g_w1h[NW];
__device__ __half g_w3h[NW];
__device__ __half g_w2h[NW];
__device__ __half g_acth[(size_t)NROWS * FF];

__device__ int   g_tokExp[TT * 2];
__device__ float g_tokW[TT * 2];
__device__ int   g_count[EE];
__device__ int   g_offset[EE];
__device__ int   g_cursor[EE];
__device__ int   g_rowTok[NROWS];
__device__ float g_rowW[NROWS];

// work queue state
__device__ int   g_qcursor;
__device__ int   g_done1[EE];

#define G1N 2048                  // gemm1 tiles per expert (32 y x 64 x)
#define G2N 256                   // gemm2 tiles per expert (32 y x 8 x)
#define TOTAL_ITEMS (EE * (G1N + G2N))   // 18432

// ================= PTX helpers (sm_80-generic only) =================
__device__ __forceinline__ u32 smem_u32(const void* p) {
    u32 a;
    asm("{ .reg .u64 t; cvta.to.shared.u64 t, %1; cvt.u32.u64 %0, t; }" : "=r"(a) : "l"(p));
    return a;
}
__device__ __forceinline__ void cp16(u32 dst, const void* src) {
    asm volatile("cp.async.cg.shared.global [%0], [%1], 16;" :: "r"(dst), "l"(src));
}
__device__ __forceinline__ void cp_commit() {
    asm volatile("cp.async.commit_group;" ::: "memory");
}
__device__ __forceinline__ void cp_wait1() {
    asm volatile("cp.async.wait_group 1;" ::: "memory");
}
__device__ __forceinline__ void cp_wait0() {
    asm volatile("cp.async.wait_group 0;" ::: "memory");
}
__device__ __forceinline__ void ldsm4(u32 addr, u32* r) {
    asm volatile("ldmatrix.sync.aligned.m8n8.x4.shared.b16 {%0,%1,%2,%3}, [%4];"
        : "=r"(r[0]), "=r"(r[1]), "=r"(r[2]), "=r"(r[3]) : "r"(addr));
}
__device__ __forceinline__ void mma16816(float* d, const u32* a, const u32* b) {
    asm volatile(
        "mma.sync.aligned.m16n8k16.row.col.f32.f16.f16.f32 "
        "{%0,%1,%2,%3}, {%4,%5,%6,%7}, {%8,%9}, {%0,%1,%2,%3};"
        : "+f"(d[0]), "+f"(d[1]), "+f"(d[2]), "+f"(d[3])
        : "r"(a[0]), "r"(a[1]), "r"(a[2]), "r"(a[3]), "r"(b[0]), "r"(b[1]));
}

#define KT     64
#define PITCH  72                     // fp16 elems per smem row (144B: conflict-free)
#define ROWB   (PITCH * 2)            // 144 bytes per row
#define A_BYTES  (128 * ROWB)         // 18432
#define W_BYTES  (64 * ROWB)          // 9216

#define G_STAGE (A_BYTES + 2 * W_BYTES)      // 36864 (both gemms)
#define G_SMEM  (1024 + 2 * G_STAGE)         // 74752

// ================= fused convert (+reset): all tensors -> fp16 ================
#define XC  (TT * DD / 4)
#define WC  (NW / 4)
__global__ void __launch_bounds__(256)
split_all_kernel(const float* __restrict__ x,  const float* __restrict__ w1,
                 const float* __restrict__ w3, const float* __restrict__ w2) {
    if (blockIdx.x == 0 && threadIdx.x < EE) {
        g_count[threadIdx.x] = 0;
        g_done1[threadIdx.x] = 0;
        if (threadIdx.x == 0) g_qcursor = 0;
    }
    size_t i = (size_t)blockIdx.x * 256 + threadIdx.x;
    const float* src;
    __half* dst;
    if (i < XC)               { src = x;  dst = g_xh; }
    else if (i < XC + WC)     { src = w1; dst = g_w1h; i -= XC; }
    else if (i < XC + 2 * WC) { src = w3; dst = g_w3h; i -= XC + WC; }
    else if (i < XC + 3 * WC) { src = w2; dst = g_w2h; i -= XC + 2 * WC; }
    else return;
    float4 v = ((const float4*)src)[i];
    __half2 h01, h23;
    h01.x = __float2half(v.x); h01.y = __float2half(v.y);
    h23.x = __float2half(v.z); h23.y = __float2half(v.w);
    ((uint2*)dst)[i] = make_uint2(*(u32*)&h01, *(u32*)&h23);
}

// ================= router =================
__global__ void router_kernel(const float* __restrict__ x,
                              const float* __restrict__ gw,
                              const float* __restrict__ gb) {
    const int t = blockIdx.x, tid = threadIdx.x;
    float acc[EE];
#pragma unroll
    for (int e = 0; e < EE; e++) acc[e] = 0.f;
    const float* xr = x + (size_t)t * DD;
    for (int d = tid; d < DD; d += 128) {
        float xv = xr[d];
#pragma unroll
        for (int e = 0; e < EE; e++) acc[e] += xv * gw[e * DD + d];
    }
    __shared__ float red[EE][128];
#pragma unroll
    for (int e = 0; e < EE; e++) red[e][tid] = acc[e];
    __syncthreads();
    for (int s = 64; s > 0; s >>= 1) {
        if (tid < s) {
#pragma unroll
            for (int e = 0; e < EE; e++) red[e][tid] += red[e][tid + s];
        }
        __syncthreads();
    }
    if (tid == 0) {
        float lg[EE]; float mx = -1e30f;
#pragma unroll
        for (int e = 0; e < EE; e++) { lg[e] = red[e][0] + gb[e]; mx = fmaxf(mx, lg[e]); }
#pragma unroll
        for (int e = 0; e < EE; e++) lg[e] = expf(lg[e] - mx);
        int i1 = 0;
#pragma unroll
        for (int e = 1; e < EE; e++) if (lg[e] > lg[i1]) i1 = e;
        int i2 = (i1 == 0) ? 1 : 0;
#pragma unroll
        for (int e = 0; e < EE; e++) if (e != i2 && e != i1 && lg[e] > lg[i2]) i2 = e;
        float p1 = lg[i1], p2 = lg[i2], inv = 1.f / (p1 + p2);
        g_tokExp[t * 2 + 0] = i1; g_tokW[t * 2 + 0] = p1 * inv;
        g_tokExp[t * 2 + 1] = i2; g_tokW[t * 2 + 1] = p2 * inv;
        atomicAdd(&g_count[i1], 1);
        atomicAdd(&g_count[i2], 1);
    }
}

// ================= fused scan + scatter (single block) =================
__global__ void scanscatter_kernel() {
    const int tid = threadIdx.x;
    if (tid == 0) {
        int off = 0;
#pragma unroll
        for (int e = 0; e < EE; e++) { g_offset[e] = off; g_cursor[e] = off; off += g_count[e]; }
    }
    __syncthreads();
    for (int t = tid; t < TT; t += 256) {
#pragma unroll
        for (int s = 0; s < 2; s++) {
            int e = g_tokExp[t * 2 + s];
            int p = atomicAdd(&g_cursor[e], 1);
            g_rowTok[p] = t;
            g_rowW[p]   = g_tokW[t * 2 + s];
        }
    }
}

// ================= gemm1 tile body =================
__device__ __forceinline__ void gemm1_tile(char* smem, int e, int yb, int xb) {
    const int cnt = g_count[e];
    const int off = g_offset[e];
    const int mB  = yb * 128;
    if (mB >= cnt) return;
    const int valid = min(128, cnt - mB);
    const int nf0   = xb * 64;
    const int tid   = threadIdx.x;
    const int wid   = tid >> 5, lane = tid & 31;

    int* tokSm = (int*)smem;
    tokSm[tid] = g_rowTok[off + mB + min(tid, valid - 1)];
    __syncthreads();

    const u32 sb = smem_u32(smem);
    const size_t wbase = (size_t)e * FF * DD + (size_t)nf0 * DD;

    const int lr0 = tid >> 3, lch = tid & 7;
    int tokR[8];
#pragma unroll
    for (int r = 0; r < 8; r++) tokR[r] = tokSm[lr0 + r * 16];

    auto load_stage = [&](int s, int k0) {
        u32 st = sb + 1024 + s * G_STAGE;
        const size_t ko = (size_t)(k0 + lch * 8);
#pragma unroll
        for (int r = 0; r < 8; r++) {
            u32 co = (u32)((lr0 + r * 16) * ROWB + lch * 16);
            cp16(st + co, &g_xh[(size_t)tokR[r] * DD + ko]);
        }
        const u32 bb = st + A_BYTES;
#pragma unroll
        for (int r = 0; r < 4; r++) {
            int row = lr0 + r * 16;
            u32 co = (u32)(row * ROWB + lch * 16);
            size_t go = wbase + (size_t)row * DD + ko;
            cp16(bb + co,           &g_w1h[go]);
            cp16(bb + W_BYTES + co, &g_w3h[go]);
        }
    };

    const int m_w = (wid >> 1) * 64, n_w = (wid & 1) * 32;
    const int lmat = lane >> 3, lr = lane & 7;
    const int aRow = m_w + (lmat & 1) * 8 + lr;
    const int aCol = (lmat >> 1) * 8;
    const int bRow = n_w + (lmat >> 1) * 8 + lr;
    const int bCol = (lmat & 1) * 8;

    float acc1[4][4][4], acc2[4][4][4];
#pragma unroll
    for (int mt = 0; mt < 4; mt++)
#pragma unroll
        for (int nt = 0; nt < 4; nt++)
#pragma unroll
            for (int q = 0; q < 4; q++) { acc1[mt][nt][q] = 0.f; acc2[mt][nt][q] = 0.f; }

    load_stage(0, 0);  cp_commit();
    load_stage(1, KT); cp_commit();

    const int NK = DD / KT;   // 16
    for (int kt = 0; kt < NK; kt++) {
        const int s = kt & 1;
        cp_wait1();
        __syncthreads();
        const u32 st = sb + 1024 + s * G_STAGE;
        const u32 bb = st + A_BYTES;
#pragma unroll
        for (int k16 = 0; k16 < KT; k16 += 16) {
            u32 aH[4][4];
#pragma unroll
            for (int mt = 0; mt < 4; mt++) {
                u32 ao = (u32)((aRow + mt * 16) * PITCH + k16 + aCol) * 2;
                ldsm4(st + ao, aH[mt]);
            }
#pragma unroll
            for (int p = 0; p < 2; p++) {
                u32 bo = (u32)((bRow + p * 16) * PITCH + k16 + bCol) * 2;
                u32 b1h[4], b3h[4];
                ldsm4(bb + bo,           b1h);
                ldsm4(bb + W_BYTES + bo, b3h);
#pragma unroll
                for (int mt = 0; mt < 4; mt++)
#pragma unroll
                    for (int q = 0; q < 2; q++) {
                        mma16816(acc1[mt][p * 2 + q], aH[mt], &b1h[q * 2]);
                        mma16816(acc2[mt][p * 2 + q], aH[mt], &b3h[q * 2]);
                    }
            }
        }
        __syncthreads();
        if (kt + 2 < NK) load_stage(s, (kt + 2) * KT);
        cp_commit();
    }
    cp_wait0();

    // epilogue: silu(h1)*h3 -> fp16 -> global
    u32* outH = (u32*)g_acth;
#pragma unroll
    for (int mt = 0; mt < 4; mt++)
#pragma unroll
        for (int rh = 0; rh < 2; rh++) {
            int rowl = m_w + mt * 16 + rh * 8 + (lane >> 2);
            if (rowl < valid) {
                size_t base = (size_t)(off + mB + rowl) * FF + nf0;
#pragma unroll
                for (int nt = 0; nt < 4; nt++) {
                    float h0 = acc1[mt][nt][rh * 2 + 0];
                    float h1 = acc1[mt][nt][rh * 2 + 1];
                    float a0 = h0 * (1.f / (1.f + __expf(-h0))) * acc2[mt][nt][rh * 2 + 0];
                    float a1 = h1 * (1.f / (1.f + __expf(-h1))) * acc2[mt][nt][rh * 2 + 1];
                    __half2 hh;
                    hh.x = __float2half(a0);
                    hh.y = __float2half(a1);
                    size_t gi = (base + n_w + nt * 8 + (lane & 3) * 2) >> 1;
                    outH[gi] = *(u32*)&hh;
                }
            }
        }
}

// ================= gemm2 tile body =================
__device__ __forceinline__ void gemm2_tile(char* smem, int e, int yb, int xb,
                                           float* __restrict__ out) {
    const int cnt = g_count[e];
    const int off = g_offset[e];
    const int mB  = yb * 128;
    if (mB >= cnt) return;
    const int valid = min(128, cnt - mB);
    const int nd0   = xb * 128;
    const int tid   = threadIdx.x;
    const int wid   = tid >> 5, lane = tid & 31;

    const u32 sb = smem_u32(smem);
    const size_t wbase = (size_t)e * DD * FF + (size_t)nd0 * FF;

    const int lr0 = tid >> 3, lch = tid & 7;
    int arowR[8];
#pragma unroll
    for (int r = 0; r < 8; r++) arowR[r] = off + mB + min(lr0 + r * 16, valid - 1);

    auto load_stage = [&](int s, int k0) {
        u32 st = sb + 1024 + s * G_STAGE;
        const size_t ko = (size_t)(k0 + lch * 8);
#pragma unroll
        for (int r = 0; r < 8; r++) {
            u32 co = (u32)((lr0 + r * 16) * ROWB + lch * 16);
            cp16(st + co, &g_acth[(size_t)arowR[r] * FF + ko]);
        }
        const u32 bb = st + A_BYTES;
#pragma unroll
        for (int r = 0; r < 8; r++) {
            int row = lr0 + r * 16;
            u32 co = (u32)(row * ROWB + lch * 16);
            cp16(bb + co, &g_w2h[wbase + (size_t)row * FF + ko]);
        }
    };

    const int m_w = (wid >> 1) * 64, n_w = (wid & 1) * 64;
    const int lmat = lane >> 3, lr = lane & 7;
    const int aRow = m_w + (lmat & 1) * 8 + lr;
    const int aCol = (lmat >> 1) * 8;
    const int bRow = n_w + (lmat >> 1) * 8 + lr;
    const int bCol = (lmat & 1) * 8;

    float acc[4][8][4];
#pragma unroll
    for (int mt = 0; mt < 4; mt++)
#pragma unroll
        for (int nt = 0; nt < 8; nt++)
#pragma unroll
            for (int q = 0; q < 4; q++) acc[mt][nt][q] = 0.f;

    load_stage(0, 0);  cp_commit();
    load_stage(1, KT); cp_commit();

    const int NK = FF / KT;   // 64
    for (int kt = 0; kt < NK; kt++) {
        const int s = kt & 1;
        cp_wait1();
        __syncthreads();
        const u32 st = sb + 1024 + s * G_STAGE;
        const u32 bb = st + A_BYTES;
#pragma unroll
        for (int k16 = 0; k16 < KT; k16 += 16) {
            u32 aH[4][4];
#pragma unroll
            for (int mt = 0; mt < 4; mt++) {
                u32 ao = (u32)((aRow + mt * 16) * PITCH + k16 + aCol) * 2;
                ldsm4(st + ao, aH[mt]);
            }
#pragma unroll
            for (int p = 0; p < 4; p++) {
                u32 bo = (u32)((bRow + p * 16) * PITCH + k16 + bCol) * 2;
                u32 bh[4];
                ldsm4(bb + bo, bh);
#pragma unroll
                for (int mt = 0; mt < 4; mt++)
#pragma unroll
                    for (int q = 0; q < 2; q++)
                        mma16816(acc[mt][p * 2 + q], aH[mt], &bh[q * 2]);
            }
        }
        __syncthreads();
        if (kt + 2 < NK) load_stage(s, (kt + 2) * KT);
        cp_commit();
    }
    cp_wait0();

    // epilogue: weighted atomic combine
#pragma unroll
    for (int mt = 0; mt < 4; mt++)
#pragma unroll
        for (int rh = 0; rh < 2; rh++) {
            int rowl = m_w + mt * 16 + rh * 8 + (lane >> 2);
            if (rowl < valid) {
                int gr = off + mB + rowl;
                int tok = g_rowTok[gr];
                float w = g_rowW[gr];
                float* op = &out[(size_t)tok * DD + nd0];
#pragma unroll
                for (int nt = 0; nt < 8; nt++) {
                    int c = n_w + nt * 8 + (lane & 3) * 2;
                    atomicAdd(op + c,     w * acc[mt][nt][rh * 2 + 0]);
                    atomicAdd(op + c + 1, w * acc[mt][nt][rh * 2 + 1]);
                }
            }
        }
}

// ============ fused persistent kernel: interleaved work queue =================
// order: g1(e0), g1(e1), g2(e0), g1(e2), g2(e1), ..., g1(e7), g2(e6), g2(e7)
// -> when g2(e) items are claimed, 2048 g1 items (~4.5 waves) separate them
//    from the last g1(e) claim, so done1[e]==2048 holds and spins are ~0.
__global__ void __launch_bounds__(128, 3)
moe_fused(float* __restrict__ out) {
    extern __shared__ char smem[];
    __shared__ int s_id;
    while (true) {
        if (threadIdx.x == 0) s_id = atomicAdd(&g_qcursor, 1);
        __syncthreads();
        const int id = s_id;
        __syncthreads();
        if (id >= TOTAL_ITEMS) return;

        // decode interleaved schedule
        int type, e, r;
        if (id < 2 * G1N) {                        // g1(e0), g1(e1)
            type = 0; e = id / G1N; r = id % G1N;
        } else if (id < 2 * G1N + 6 * (G1N + G2N)) {   // [g1(e_{b+2}) | g2(e_b)] x6
            int j = id - 2 * G1N;
            int b = j / (G1N + G2N);
            int q = j % (G1N + G2N);
            if (q < G1N) { type = 0; e = b + 2; r = q; }
            else         { type = 1; e = b;     r = q - G1N; }
        } else {                                    // g2(e6), g2(e7)
            int j = id - (2 * G1N + 6 * (G1N + G2N));
            type = 1; e = 6 + j / G2N; r = j % G2N;
        }

        if (type == 0) {
            gemm1_tile(smem, e, r >> 6, r & 63);   // 32 y x 64 x  (FIXED decode)
            __syncthreads();
            if (threadIdx.x == 0) {
                __threadfence();
                atomicAdd(&g_done1[e], 1);
            }
        } else {
            if (threadIdx.x == 0) {
                while (*(volatile int*)&g_done1[e] < G1N) __nanosleep(100);
            }
            __syncthreads();
            __threadfence();
            gemm2_tile(smem, e, r >> 3, r & 7, out);   // 32 y x 8 x
        }
        __syncthreads();
    }
}

// ================= host =================
extern "C" void kernel_launch(void* const* d_in, const int* in_sizes, int n_in,
                              void* d_out, int out_size) {
    const float* x  = (const float*)d_in[0];
    const float* gw = (const float*)d_in[1];
    const float* gb = (const float*)d_in[2];
    const float* w1 = (const float*)d_in[3];
    const float* w3 = (const float*)d_in[4];
    const float* w2 = (const float*)d_in[5];
    float* out = (float*)d_out;

    cudaFuncSetAttribute(moe_fused, cudaFuncAttributeMaxDynamicSharedMemorySize, G_SMEM);

    cudaMemsetAsync(out, 0, (size_t)out_size * sizeof(float), 0);

    const size_t totalChunks = (size_t)XC + 3 * (size_t)WC;
    split_all_kernel<<<(unsigned)((totalChunks + 255) / 256), 256>>>(x, w1, w3, w2);

    router_kernel<<<TT, 128>>>(x, gw, gb);
    scanscatter_kernel<<<1, 256>>>();

    moe_fused<<<456, 128, G_SMEM>>>(out);   // 152 SMs x 3 resident CTAs
}

// round 17
// speedup vs baseline: 1.1654x; 1.1654x over previous
#include <cuda_runtime.h>
#include <cuda_fp16.h>

#define TT 4096
#define DD 1024
#define FF 4096
#define EE 8
#define NROWS (TT * 2)
#define NW   (EE * FF * DD)

typedef unsigned int u32;

// ================= device scratch (static) =================
__device__ __half g_xh[TT * DD];
__device__ __half g_w1h[NW];
__device__ __half g_w3h[NW];
__device__ __half g_w2h[NW];
__device__ __half g_acth[(size_t)NROWS * FF];

__device__ int   g_tokExp[TT * 2];
__device__ float g_tokW[TT * 2];
__device__ int   g_count[EE];
__device__ int   g_offset[EE];
__device__ int   g_cursor[EE];
__device__ int   g_rowTok[NROWS];
__device__ float g_rowW[NROWS];

// ================= PTX helpers (sm_80-generic only) =================
__device__ __forceinline__ u32 smem_u32(const void* p) {
    u32 a;
    asm("{ .reg .u64 t; cvta.to.shared.u64 t, %1; cvt.u32.u64 %0, t; }" : "=r"(a) : "l"(p));
    return a;
}
__device__ __forceinline__ void cp16(u32 dst, const void* src) {
    asm volatile("cp.async.cg.shared.global [%0], [%1], 16;" :: "r"(dst), "l"(src));
}
__device__ __forceinline__ void cp_commit() {
    asm volatile("cp.async.commit_group;" ::: "memory");
}
__device__ __forceinline__ void cp_wait1() {
    asm volatile("cp.async.wait_group 1;" ::: "memory");
}
__device__ __forceinline__ void ldsm4(u32 addr, u32* r) {
    asm volatile("ldmatrix.sync.aligned.m8n8.x4.shared.b16 {%0,%1,%2,%3}, [%4];"
        : "=r"(r[0]), "=r"(r[1]), "=r"(r[2]), "=r"(r[3]) : "r"(addr));
}
__device__ __forceinline__ void mma16816(float* d, const u32* a, const u32* b) {
    asm volatile(
        "mma.sync.aligned.m16n8k16.row.col.f32.f16.f16.f32 "
        "{%0,%1,%2,%3}, {%4,%5,%6,%7}, {%8,%9}, {%0,%1,%2,%3};"
        : "+f"(d[0]), "+f"(d[1]), "+f"(d[2]), "+f"(d[3])
        : "r"(a[0]), "r"(a[1]), "r"(a[2]), "r"(a[3]), "r"(b[0]), "r"(b[1]));
}

#define KT     64
#define PITCH  72                     // fp16 elems per smem row (144B: conflict-free)
#define ROWB   (PITCH * 2)            // 144 bytes per row
#define A_BYTES  (128 * ROWB)         // 18432
#define W_BYTES  (64 * ROWB)          // 9216

// ================= weights -> fp16 (x handled by router) =================
#define WC  (NW / 4)
__global__ void __launch_bounds__(256)
split_w_kernel(const float* __restrict__ w1,
               const float* __restrict__ w3,
               const float* __restrict__ w2) {
    if (blockIdx.x == 0 && threadIdx.x < EE) g_count[threadIdx.x] = 0;
    size_t i = (size_t)blockIdx.x * 256 + threadIdx.x;
    const float* src;
    __half* dst;
    if (i < WC)               { src = w1; dst = g_w1h; }
    else if (i < 2 * WC)      { src = w3; dst = g_w3h; i -= WC; }
    else if (i < 3 * WC)      { src = w2; dst = g_w2h; i -= 2 * WC; }
    else return;
    float4 v = ((const float4*)src)[i];
    __half2 h01, h23;
    h01.x = __float2half(v.x); h01.y = __float2half(v.y);
    h23.x = __float2half(v.z); h23.y = __float2half(v.w);
    ((uint2*)dst)[i] = make_uint2(*(u32*)&h01, *(u32*)&h23);
}

// ================= router (also emits g_xh) =================
__global__ void router_kernel(const float* __restrict__ x,
                              const float* __restrict__ gw,
                              const float* __restrict__ gb) {
    const int t = blockIdx.x, tid = threadIdx.x;
    float acc[EE];
#pragma unroll
    for (int e = 0; e < EE; e++) acc[e] = 0.f;
    const float* xr = x + (size_t)t * DD;
    __half* xo = g_xh + (size_t)t * DD;
    for (int d = tid * 2; d < DD; d += 256) {
        float xv0 = xr[d], xv1 = xr[d + 1];
        __half2 h;
        h.x = __float2half(xv0);
        h.y = __float2half(xv1);
        *(u32*)&xo[d] = *(u32*)&h;
#pragma unroll
        for (int e = 0; e < EE; e++)
            acc[e] += xv0 * gw[e * DD + d] + xv1 * gw[e * DD + d + 1];
    }
    __shared__ float red[EE][128];
#pragma unroll
    for (int e = 0; e < EE; e++) red[e][tid] = acc[e];
    __syncthreads();
    for (int s = 64; s > 0; s >>= 1) {
        if (tid < s) {
#pragma unroll
            for (int e = 0; e < EE; e++) red[e][tid] += red[e][tid + s];
        }
        __syncthreads();
    }
    if (tid == 0) {
        float lg[EE]; float mx = -1e30f;
#pragma unroll
        for (int e = 0; e < EE; e++) { lg[e] = red[e][0] + gb[e]; mx = fmaxf(mx, lg[e]); }
#pragma unroll
        for (int e = 0; e < EE; e++) lg[e] = expf(lg[e] - mx);
        int i1 = 0;
#pragma unroll
        for (int e = 1; e < EE; e++) if (lg[e] > lg[i1]) i1 = e;
        int i2 = (i1 == 0) ? 1 : 0;
#pragma unroll
        for (int e = 0; e < EE; e++) if (e != i2 && e != i1 && lg[e] > lg[i2]) i2 = e;
        float p1 = lg[i1], p2 = lg[i2], inv = 1.f / (p1 + p2);
        g_tokExp[t * 2 + 0] = i1; g_tokW[t * 2 + 0] = p1 * inv;
        g_tokExp[t * 2 + 1] = i2; g_tokW[t * 2 + 1] = p2 * inv;
        atomicAdd(&g_count[i1], 1);
        atomicAdd(&g_count[i2], 1);
    }
}

// ================= fused scan + scatter (single block) =================
__global__ void scanscatter_kernel() {
    const int tid = threadIdx.x;
    if (tid == 0) {
        int off = 0;
#pragma unroll
        for (int e = 0; e < EE; e++) { g_offset[e] = off; g_cursor[e] = off; off += g_count[e]; }
    }
    __syncthreads();
    for (int t = tid; t < TT; t += 256) {
#pragma unroll
        for (int s = 0; s < 2; s++) {
            int e = g_tokExp[t * 2 + s];
            int p = atomicAdd(&g_cursor[e], 1);
            g_rowTok[p] = t;
            g_rowW[p]   = g_tokW[t * 2 + s];
        }
    }
}

// ====== GEMM1: block 128x64, 128 thr, warp 64x32 dual, 2-stage, 3 CTA/SM ======
#define G1_STAGE (A_BYTES + 2 * W_BYTES)      // 36864
#define G1_SMEM  (1024 + 2 * G1_STAGE)        // 74752

__global__ void __launch_bounds__(128, 3)
gemm1_mma() {
    extern __shared__ char smem[];
    const int e   = blockIdx.z;
    const int cnt = g_count[e];
    const int off = g_offset[e];
    const int mB  = blockIdx.y * 128;
    if (mB >= cnt) return;
    const int valid = min(128, cnt - mB);
    const int nf0   = blockIdx.x * 64;
    const int tid   = threadIdx.x;
    const int wid   = tid >> 5, lane = tid & 31;

    int* tokSm = (int*)smem;
    tokSm[tid] = g_rowTok[off + mB + min(tid, valid - 1)];
    __syncthreads();

    const u32 sb = smem_u32(smem);
    const size_t wbase = (size_t)e * FF * DD + (size_t)nf0 * DD;

    const int lr0 = tid >> 3, lch = tid & 7;
    int tokR[8];
#pragma unroll
    for (int r = 0; r < 8; r++) tokR[r] = tokSm[lr0 + r * 16];

    auto load_stage = [&](int s, int k0) {
        u32 st = sb + 1024 + s * G1_STAGE;
        const size_t ko = (size_t)(k0 + lch * 8);
#pragma unroll
        for (int r = 0; r < 8; r++) {
            u32 co = (u32)((lr0 + r * 16) * ROWB + lch * 16);
            cp16(st + co, &g_xh[(size_t)tokR[r] * DD + ko]);
        }
        const u32 bb = st + A_BYTES;
#pragma unroll
        for (int r = 0; r < 4; r++) {
            int row = lr0 + r * 16;
            u32 co = (u32)(row * ROWB + lch * 16);
            size_t go = wbase + (size_t)row * DD + ko;
            cp16(bb + co,           &g_w1h[go]);
            cp16(bb + W_BYTES + co, &g_w3h[go]);
        }
    };

    const int m_w = (wid >> 1) * 64, n_w = (wid & 1) * 32;
    const int lmat = lane >> 3, lr = lane & 7;
    const int aRow = m_w + (lmat & 1) * 8 + lr;
    const int aCol = (lmat >> 1) * 8;
    const int bRow = n_w + (lmat >> 1) * 8 + lr;
    const int bCol = (lmat & 1) * 8;

    float acc1[4][4][4], acc2[4][4][4];
#pragma unroll
    for (int mt = 0; mt < 4; mt++)
#pragma unroll
        for (int nt = 0; nt < 4; nt++)
#pragma unroll
            for (int q = 0; q < 4; q++) { acc1[mt][nt][q] = 0.f; acc2[mt][nt][q] = 0.f; }

    load_stage(0, 0);  cp_commit();
    load_stage(1, KT); cp_commit();

    const int NK = DD / KT;   // 16
    for (int kt = 0; kt < NK; kt++) {
        const int s = kt & 1;
        cp_wait1();
        __syncthreads();
        const u32 st = sb + 1024 + s * G1_STAGE;
        const u32 bb = st + A_BYTES;
#pragma unroll
        for (int k16 = 0; k16 < KT; k16 += 16) {
            u32 aH[4][4];
#pragma unroll
            for (int mt = 0; mt < 4; mt++) {
                u32 ao = (u32)((aRow + mt * 16) * PITCH + k16 + aCol) * 2;
                ldsm4(st + ao, aH[mt]);
            }
#pragma unroll
            for (int p = 0; p < 2; p++) {
                u32 bo = (u32)((bRow + p * 16) * PITCH + k16 + bCol) * 2;
                u32 b1h[4], b3h[4];
                ldsm4(bb + bo,           b1h);
                ldsm4(bb + W_BYTES + bo, b3h);
#pragma unroll
                for (int mt = 0; mt < 4; mt++)
#pragma unroll
                    for (int q = 0; q < 2; q++) {
                        mma16816(acc1[mt][p * 2 + q], aH[mt], &b1h[q * 2]);
                        mma16816(acc2[mt][p * 2 + q], aH[mt], &b3h[q * 2]);
                    }
            }
        }
        __syncthreads();
        if (kt + 2 < NK) load_stage(s, (kt + 2) * KT);
        cp_commit();
    }

    // epilogue: silu(h1)*h3 -> fp16 -> global
    u32* outH = (u32*)g_acth;
#pragma unroll
    for (int mt = 0; mt < 4; mt++)
#pragma unroll
        for (int rh = 0; rh < 2; rh++) {
            int rowl = m_w + mt * 16 + rh * 8 + (lane >> 2);
            if (rowl < valid) {
                size_t base = (size_t)(off + mB + rowl) * FF + nf0;
#pragma unroll
                for (int nt = 0; nt < 4; nt++) {
                    float h0 = acc1[mt][nt][rh * 2 + 0];
                    float h1 = acc1[mt][nt][rh * 2 + 1];
                    float a0 = h0 * (1.f / (1.f + __expf(-h0))) * acc2[mt][nt][rh * 2 + 0];
                    float a1 = h1 * (1.f / (1.f + __expf(-h1))) * acc2[mt][nt][rh * 2 + 1];
                    __half2 hh;
                    hh.x = __float2half(a0);
                    hh.y = __float2half(a1);
                    size_t gi = (base + n_w + nt * 8 + (lane & 3) * 2) >> 1;
                    outH[gi] = *(u32*)&hh;
                }
            }
        }
}

// ====== GEMM2: block 128x128, 128 thr, warp 64x64 single, 2-stage, 3 CTA/SM ===
#define G2_STAGE (2 * A_BYTES)                // 36864
#define G2_SMEM  (1024 + 2 * G2_STAGE)        // 74752

__global__ void __launch_bounds__(128, 3)
gemm2_mma(float* __restrict__ out) {
    extern __shared__ char smem[];
    const int e   = blockIdx.z;
    const int cnt = g_count[e];
    const int off = g_offset[e];
    const int mB  = blockIdx.y * 128;
    if (mB >= cnt) return;
    const int valid = min(128, cnt - mB);
    const int nd0   = blockIdx.x * 128;
    const int tid   = threadIdx.x;
    const int wid   = tid >> 5, lane = tid & 31;

    const u32 sb = smem_u32(smem);
    const size_t wbase = (size_t)e * DD * FF + (size_t)nd0 * FF;

    const int lr0 = tid >> 3, lch = tid & 7;
    int arowR[8];
#pragma unroll
    for (int r = 0; r < 8; r++) arowR[r] = off + mB + min(lr0 + r * 16, valid - 1);

    auto load_stage = [&](int s, int k0) {
        u32 st = sb + 1024 + s * G2_STAGE;
        const size_t ko = (size_t)(k0 + lch * 8);
#pragma unroll
        for (int r = 0; r < 8; r++) {
            u32 co = (u32)((lr0 + r * 16) * ROWB + lch * 16);
            cp16(st + co, &g_acth[(size_t)arowR[r] * FF + ko]);
        }
        const u32 bb = st + A_BYTES;
#pragma unroll
        for (int r = 0; r < 8; r++) {
            int row = lr0 + r * 16;
            u32 co = (u32)(row * ROWB + lch * 16);
            cp16(bb + co, &g_w2h[wbase + (size_t)row * FF + ko]);
        }
    };

    const int m_w = (wid >> 1) * 64, n_w = (wid & 1) * 64;
    const int lmat = lane >> 3, lr = lane & 7;
    const int aRow = m_w + (lmat & 1) * 8 + lr;
    const int aCol = (lmat >> 1) * 8;
    const int bRow = n_w + (lmat >> 1) * 8 + lr;
    const int bCol = (lmat & 1) * 8;

    float acc[4][8][4];
#pragma unroll
    for (int mt = 0; mt < 4; mt++)
#pragma unroll
        for (int nt = 0; nt < 8; nt++)
#pragma unroll
            for (int q = 0; q < 4; q++) acc[mt][nt][q] = 0.f;

    load_stage(0, 0);  cp_commit();
    load_stage(1, KT); cp_commit();

    const int NK = FF / KT;   // 64
    for (int kt = 0; kt < NK; kt++) {
        const int s = kt & 1;
        cp_wait1();
        __syncthreads();
        const u32 st = sb + 1024 + s * G2_STAGE;
        const u32 bb = st + A_BYTES;
#pragma unroll
        for (int k16 = 0; k16 < KT; k16 += 16) {
            u32 aH[4][4];
#pragma unroll
            for (int mt = 0; mt < 4; mt++) {
                u32 ao = (u32)((aRow + mt * 16) * PITCH + k16 + aCol) * 2;
                ldsm4(st + ao, aH[mt]);
            }
#pragma unroll
            for (int p = 0; p < 4; p++) {
                u32 bo = (u32)((bRow + p * 16) * PITCH + k16 + bCol) * 2;
                u32 bh[4];
                ldsm4(bb + bo, bh);
#pragma unroll
                for (int mt = 0; mt < 4; mt++)
#pragma unroll
                    for (int q = 0; q < 2; q++)
                        mma16816(acc[mt][p * 2 + q], aH[mt], &bh[q * 2]);
            }
        }
        __syncthreads();
        if (kt + 2 < NK) load_stage(s, (kt + 2) * KT);
        cp_commit();
    }

    // epilogue: weighted atomic combine
#pragma unroll
    for (int mt = 0; mt < 4; mt++)
#pragma unroll
        for (int rh = 0; rh < 2; rh++) {
            int rowl = m_w + mt * 16 + rh * 8 + (lane >> 2);
            if (rowl < valid) {
                int gr = off + mB + rowl;
                int tok = g_rowTok[gr];
                float w = g_rowW[gr];
                float* op = &out[(size_t)tok * DD + nd0];
#pragma unroll
                for (int nt = 0; nt < 8; nt++) {
                    int c = n_w + nt * 8 + (lane & 3) * 2;
                    atomicAdd(op + c,     w * acc[mt][nt][rh * 2 + 0]);
                    atomicAdd(op + c + 1, w * acc[mt][nt][rh * 2 + 1]);
                }
            }
        }
}

// ================= host =================
extern "C" void kernel_launch(void* const* d_in, const int* in_sizes, int n_in,
                              void* d_out, int out_size) {
    const float* x  = (const float*)d_in[0];
    const float* gw = (const float*)d_in[1];
    const float* gb = (const float*)d_in[2];
    const float* w1 = (const float*)d_in[3];
    const float* w3 = (const float*)d_in[4];
    const float* w2 = (const float*)d_in[5];
    float* out = (float*)d_out;

    cudaFuncSetAttribute(gemm1_mma, cudaFuncAttributeMaxDynamicSharedMemorySize, G1_SMEM);
    cudaFuncSetAttribute(gemm2_mma, cudaFuncAttributeMaxDynamicSharedMemorySize, G2_SMEM);

    cudaMemsetAsync(out, 0, (size_t)out_size * sizeof(float), 0);

    // weights conversion first (longest pre-GEMM kernel; also resets g_count)
    split_w_kernel<<<(unsigned)((3 * (size_t)WC + 255) / 256), 256>>>(w1, w3, w2);

    // router also converts x -> g_xh
    router_kernel<<<TT, 128>>>(x, gw, gb);
    scanscatter_kernel<<<1, 256>>>();

    dim3 g1(FF / 64, 32, EE);        // block 128 rows x 64 cols
    gemm1_mma<<<g1, 128, G1_SMEM>>>();
    dim3 g2(DD / 128, 32, EE);       // block 128 rows x 128 cols
    gemm2_mma<<<g2, 128, G2_SMEM>>>(out);
}